// round 15
// baseline (speedup 1.0000x reference)
#include <cuda_runtime.h>
#include <cuda_bf16.h>
#include <math.h>
#include <stdint.h>

#define S_LEN 2048
#define HID   256
#define BN    16
#define M_ROWS (BN * S_LEN)   // 32768

#define L2G  (-0.04580369f)              // log2(0.96875)
#define IGAM (1.03225806451612903f)      // 1/0.96875
#define G8C  (0.775700596198439598f)     // 0.96875^8 (exact)

// ---------------------------------------------------------------------------
// Device-global scratch: PRE-SWIZZLED smem-image tiles.
// Image rule: byte offset of (row, col byte-pair unit) = row*R + (colb ^ ((row&7)<<4))
//   X images: [tile256][chunk4][plane2][128 rows x 128B]   (R=128)
//   W images: [mode3][chunk4][plane2][64 rows x 512B]      (R=512)
//   Q/K/V images: [bn16][tile64][plane2][32 rows x 512B]   (R=512)
// ---------------------------------------------------------------------------
__device__ __align__(256) uint8_t g_Xi[33554432];
__device__ __align__(256) uint8_t g_Wi[786432];
__device__ __align__(256) uint8_t g_Qi[33554432];
__device__ __align__(256) uint8_t g_Ki[33554432];
__device__ __align__(256) uint8_t g_Vi[33554432];
__device__ float4 g_tab[S_LEN * 128];   // {sin, cos, scale, 1/scale}

// ---------------------------------------------------------------------------
// helpers
// ---------------------------------------------------------------------------
__device__ __forceinline__ uint32_t smem_u32(const void* p) {
    uint32_t a;
    asm("{ .reg .u64 t; cvta.to.shared.u64 t, %1; cvt.u32.u64 %0, t; }" : "=r"(a) : "l"(p));
    return a;
}
#define MBAR_INIT(mb, c) asm volatile("mbarrier.init.shared.b64 [%0], %1;" :: "r"(mb), "r"((uint32_t)(c)) : "memory")
#define MBAR_EXPECT(mb, bytes) \
    asm volatile("mbarrier.arrive.expect_tx.shared.b64 _, [%0], %1;" :: "r"(mb), "r"((uint32_t)(bytes)) : "memory")

__device__ __forceinline__ void bulk_g2s(uint32_t dst, const void* src, uint32_t bytes, uint32_t mbar) {
    asm volatile("cp.async.bulk.shared::cluster.global.mbarrier::complete_tx::bytes [%0], [%1], %2, [%3];"
                 :: "r"(dst), "l"(src), "r"(bytes), "r"(mbar) : "memory");
}
__device__ __forceinline__ void mbar_wait(uint32_t mb, uint32_t ph) {
    uint32_t done;
    asm volatile("{\n\t.reg .pred p;\n\tmbarrier.try_wait.parity.acquire.cta.shared::cta.b64 p, [%1], %2;\n\tselp.b32 %0, 1, 0, p;\n\t}"
                 : "=r"(done) : "r"(mb), "r"(ph) : "memory");
    if (!done) {
        asm volatile("{\n\t.reg .pred P1;\n\tWL%=:\n\tmbarrier.try_wait.parity.acquire.cta.shared::cta.b64 P1, [%0], %1, 0x989680;\n\t@P1 bra.uni WD%=;\n\tbra.uni WL%=;\n\tWD%=:\n\t}"
                     :: "r"(mb), "r"(ph) : "memory");
    }
}
__device__ __forceinline__ void ldsm4(uint32_t* r, uint32_t a) {
    asm volatile("ldmatrix.sync.aligned.m8n8.x4.shared.b16 {%0,%1,%2,%3}, [%4];"
                 : "=r"(r[0]), "=r"(r[1]), "=r"(r[2]), "=r"(r[3]) : "r"(a));
}
__device__ __forceinline__ void ldsm4t(uint32_t* r, uint32_t a) {
    asm volatile("ldmatrix.sync.aligned.m8n8.x4.trans.shared.b16 {%0,%1,%2,%3}, [%4];"
                 : "=r"(r[0]), "=r"(r[1]), "=r"(r[2]), "=r"(r[3]) : "r"(a));
}
__device__ __forceinline__ void mma16816(float* c, const uint32_t* a, const uint32_t* b) {
    asm volatile("mma.sync.aligned.m16n8k16.row.col.f32.bf16.bf16.f32 "
                 "{%0,%1,%2,%3}, {%4,%5,%6,%7}, {%8,%9}, {%0,%1,%2,%3};"
                 : "+f"(c[0]), "+f"(c[1]), "+f"(c[2]), "+f"(c[3])
                 : "r"(a[0]), "r"(a[1]), "r"(a[2]), "r"(a[3]), "r"(b[0]), "r"(b[1]));
}
__device__ __forceinline__ void split2(float a, float b, uint32_t& h, uint32_t& l) {
    __nv_bfloat162 hh = __floats2bfloat162_rn(a, b);
    __nv_bfloat162 ll = __floats2bfloat162_rn(a - __bfloat162float(hh.x),
                                              b - __bfloat162float(hh.y));
    h = *(uint32_t*)&hh;
    l = *(uint32_t*)&ll;
}

// ---------------------------------------------------------------------------
// Fused prep: X images | xpos table | W images (new [mode][chunk][plane] layout)
// ---------------------------------------------------------------------------
__global__ void prep_kernel(const float* __restrict__ X,
                            const float* __restrict__ Wq,
                            const float* __restrict__ Wk,
                            const float* __restrict__ Wv) {
    int b = blockIdx.x;
    if (b < 4096) {
#pragma unroll
        for (int j = 0; j < 2; j++) {
            size_t i = ((size_t)b * 512 + threadIdx.x + j * 256) * 4;
            float4 v = *(const float4*)(X + i);
            uint2 hw, lw;
            split2(v.x, v.y, hw.x, lw.x);
            split2(v.z, v.w, hw.y, lw.y);
            int row = (int)(i >> 8), k0 = (int)(i & 255);
            int tile = row >> 7, r = row & 127;
            int chunk = k0 >> 6, kk = k0 & 63;
            uint32_t m = (uint32_t)((r & 7) << 4);
            uint32_t off = (uint32_t)(((tile * 4 + chunk) * 2) * 16384)
                         + (uint32_t)(r * 128) + (((uint32_t)(kk * 2)) ^ m);
            *(uint2*)(g_Xi + off)         = hw;
            *(uint2*)(g_Xi + off + 16384) = lw;
        }
    } else if (b < 5120) {
        int idx = (b - 4096) * 256 + threadIdx.x;
        int s = idx >> 7, i = idx & 127;
        float inv_freq = (float)exp2(-(double)i * (13.287712379549449 / 128.0));
        float sn, cs;
        sincosf((float)s * inv_freq, &sn, &cs);
        float base  = ((float)(2 * i) + 102.4f) / 358.4f;
        float scale = exp2f(log2f(base) * ((float)s * (1.0f / 512.0f)));
        g_tab[idx] = make_float4(sn, cs, scale, 1.0f / scale);
    } else {
        int idx = (b - 5120) * 256 + threadIdx.x;
        int mode = idx >> 15, pos = (idx & 32767) * 2;
        const float* W = (mode == 0) ? Wq : (mode == 1) ? Wk : Wv;
        float a = W[pos], c = W[pos + 1];
        uint32_t h, l;
        split2(a, c, h, l);
        int k = pos >> 8, n = pos & 255;
        int chunk = k >> 6, kr = k & 63;
        uint32_t m = (uint32_t)((kr & 7) << 4);
        uint32_t off = (uint32_t)(mode * 262144 + chunk * 65536)
                     + (uint32_t)(kr * 512) + (((uint32_t)(n * 2)) ^ m);
        *(uint32_t*)(g_Wi + off)         = h;
        *(uint32_t*)(g_Wi + off + 32768) = l;
    }
}

// ---------------------------------------------------------------------------
// Tensor-core QKV projection: full-N CTA (128 rows x 256 cols), TMA-bulk
// double-buffered K-chunks of 64, split-3 bf16 mma.sync, frag-pipelined,
// fused xpos epilogue. grid (3 modes, 256 row-tiles), mode fastest.
// smem: 2 x (32K X + 64K W) = 192 KB.
// ---------------------------------------------------------------------------
#define PROJ_SMEM 196608

__global__ void __launch_bounds__(256, 1) proj_kernel() {
    extern __shared__ __align__(128) uint8_t smp[];
    __shared__ __align__(8) uint64_t mbs[2];
    uint32_t sb = smem_u32(smp);
    int t = threadIdx.x, wid = t >> 5, l = t & 31;
    int mode = blockIdx.x;
    int tile = blockIdx.y;

    if (t == 0) {
        MBAR_INIT(smem_u32(&mbs[0]), 1);
        MBAR_INIT(smem_u32(&mbs[1]), 1);
    }
    __syncthreads();

    const uint8_t* xsrc = g_Xi + (size_t)(tile * 4) * 32768;
    const uint8_t* wsrc = g_Wi + (size_t)mode * 262144;

    if (t == 0) {
#pragma unroll
        for (int c = 0; c < 2; c++) {
            uint32_t mb = smem_u32(&mbs[c]);
            MBAR_EXPECT(mb, 98304);
            bulk_g2s(sb + c * 98304,         xsrc + c * 32768, 32768, mb);
            bulk_g2s(sb + c * 98304 + 32768, wsrc + c * 65536, 65536, mb);
        }
    }

    int rowA = (l & 7) + ((l >> 3) & 1) * 8;
    int colA = (l >> 4) * 8;
    uint32_t mX = (uint32_t)((rowA & 7) << 4);

    float o[32][4];
#pragma unroll
    for (int i = 0; i < 32; i++)
#pragma unroll
        for (int j = 0; j < 4; j++) o[i][j] = 0.f;

    for (int ch = 0; ch < 4; ch++) {
        int bf = ch & 1;
        mbar_wait(smem_u32(&mbs[bf]), (uint32_t)((ch >> 1) & 1));

        uint32_t sX = sb + bf * 98304;
        uint32_t sW = sX + 32768;
        uint32_t xh = sX + (uint32_t)((wid * 16 + rowA) * 128);
        uint32_t xl = xh + 16384;

        // fragment-pipelined: flatten (ks 0..3, nb 0..15)
        uint32_t aH[2][4], aL[2][4], bh[2][4], bl[2][4];
        {
            uint32_t cbX = ((uint32_t)(colA * 2)) ^ mX;
            ldsm4(aH[0], xh + cbX);
            ldsm4(aL[0], xl + cbX);
            uint32_t cbW = ((uint32_t)(colA * 2)) ^ mX;
            ldsm4t(bh[0], sW + (uint32_t)(rowA * 512) + cbW);
            ldsm4t(bl[0], sW + 32768 + (uint32_t)(rowA * 512) + cbW);
        }
#pragma unroll
        for (int idx = 0; idx < 64; idx++) {
            int ks = idx >> 4, nb = idx & 15;
            int cur = idx & 1, nxt = cur ^ 1;
            int ksc = ks & 1;
            if (idx < 63) {
                int ks1 = (idx + 1) >> 4, nb1 = (idx + 1) & 15;
                uint32_t wrow1 = sW + (uint32_t)((rowA + ks1 * 16) * 512);
                uint32_t cbW1 = ((uint32_t)(colA * 2 + nb1 * 32)) ^ mX;
                ldsm4t(bh[nxt], wrow1 + cbW1);
                ldsm4t(bl[nxt], wrow1 + 32768 + cbW1);
                if (nb1 == 0) {   // new ks: prefetch A frags
                    uint32_t cbX1 = ((uint32_t)(colA * 2 + ks1 * 32)) ^ mX;
                    ldsm4(aH[ks1 & 1], xh + cbX1);
                    ldsm4(aL[ks1 & 1], xl + cbX1);
                }
            }
            mma16816(o[2 * nb],     aH[ksc], bh[cur]);
            mma16816(o[2 * nb],     aH[ksc], bl[cur]);
            mma16816(o[2 * nb],     aL[ksc], bh[cur]);
            mma16816(o[2 * nb + 1], aH[ksc], bh[cur] + 2);
            mma16816(o[2 * nb + 1], aH[ksc], bl[cur] + 2);
            mma16816(o[2 * nb + 1], aL[ksc], bh[cur] + 2);
        }
        __syncthreads();            // buffer consumed by all warps
        if (ch + 2 < 4 && t == 0) {
            uint32_t mb = smem_u32(&mbs[bf]);
            MBAR_EXPECT(mb, 98304);
            bulk_g2s(sb + bf * 98304,         xsrc + (ch + 2) * 32768, 32768, mb);
            bulk_g2s(sb + bf * 98304 + 32768, wsrc + (ch + 2) * 65536, 65536, mb);
        }
    }

    // ---- epilogue: optional xpos rotation, split, store to Q/K/V images ----
    uint8_t* img = (mode == 0) ? g_Qi : (mode == 1) ? g_Ki : g_Vi;
    int tileg = (tile >> 4) * 64 + (tile & 15) * 4 + (wid >> 1);
    int r5 = (wid & 1) * 16 + (l >> 2);
    uint32_t m5 = (uint32_t)(((l >> 2) & 7) << 4);
    uint8_t* tb = img + (size_t)(tileg * 2) * 16384;
    int s1 = (tile & 15) * 128 + wid * 16 + (l >> 2);
    int s2 = s1 + 8;

#pragma unroll
    for (int nb = 0; nb < 32; nb++) {
        int col = nb * 8 + 2 * (l & 3);
        float a0 = o[nb][0], a1 = o[nb][1];
        float b0 = o[nb][2], b1 = o[nb][3];
        if (mode != 2) {
            float4 t1 = g_tab[s1 * 128 + (col >> 1)];
            float4 t2 = g_tab[s2 * 128 + (col >> 1)];
            float sc1 = (mode == 0) ? t1.z : t1.w;
            float sc2 = (mode == 0) ? t2.z : t2.w;
            float sn1 = t1.x * sc1, cs1 = t1.y * sc1;
            float sn2 = t2.x * sc2, cs2 = t2.y * sc2;
            float n0 = a0 * cs1 - a1 * sn1;
            float n1 = a1 * cs1 + a0 * sn1;
            float m0 = b0 * cs2 - b1 * sn2;
            float m1 = b1 * cs2 + b0 * sn2;
            a0 = n0; a1 = n1; b0 = m0; b1 = m1;
        }
        uint32_t h1, l1, h2, l2;
        split2(a0, a1, h1, l1);
        split2(b0, b1, h2, l2);
        uint32_t offc = ((uint32_t)(col * 2)) ^ m5;
        *(uint32_t*)(tb + r5 * 512 + offc)               = h1;
        *(uint32_t*)(tb + 16384 + r5 * 512 + offc)       = l1;
        *(uint32_t*)(tb + (r5 + 8) * 512 + offc)         = h2;
        *(uint32_t*)(tb + 16384 + (r5 + 8) * 512 + offc) = l2;
    }
}

// ---------------------------------------------------------------------------
// Raw mma.sync retention attention, frag-pipelined, K DOUBLE-BUFFERED.
// smem: Q 128K + K0 32K + K1 32K + V 32K = 224K, 1 CTA/SM.
// ---------------------------------------------------------------------------
#define ATTN_SMEM 229376

__global__ void __launch_bounds__(256, 1) attn_kernel(float* __restrict__ out) {
    extern __shared__ __align__(128) uint8_t sma[];
    __shared__ __align__(8) uint64_t mba[4];   // Q, K0, K1, V
    uint32_t sb = smem_u32(sma);
    int t = threadIdx.x, wid = t >> 5, l = t & 31;

    int qt = 15 - (blockIdx.x >> 4);   // heavy q-tiles first
    int bn = blockIdx.x & 15;
    int jlo = max(0, qt * 4 - 8);      // drop d >= 257 (xpos damps further)
    int jhi = qt * 4 + 3;

    if (t == 0) {
#pragma unroll
        for (int i = 0; i < 4; i++) MBAR_INIT(smem_u32(&mba[i]), 1);
    }
    __syncthreads();
    uint32_t mbQ  = smem_u32(&mba[0]);
    uint32_t mbK0 = smem_u32(&mba[1]);
    uint32_t mbK1 = smem_u32(&mba[2]);
    uint32_t mbV  = smem_u32(&mba[3]);

    const uint8_t* qsrc = g_Qi + (size_t)((bn * 64 + qt * 4) * 2) * 16384;
    const uint8_t* ksrc = g_Ki + (size_t)(bn * 64 * 2) * 16384;
    const uint8_t* vsrc = g_Vi + (size_t)(bn * 64 * 2) * 16384;

    if (t == 0) {
        MBAR_EXPECT(mbQ, 131072);
        bulk_g2s(sb, qsrc, 131072, mbQ);
        MBAR_EXPECT(mbK0, 32768);
        bulk_g2s(sb + 131072, ksrc + (size_t)jlo * 32768, 32768, mbK0);
        MBAR_EXPECT(mbK1, 32768);
        bulk_g2s(sb + 163840, ksrc + (size_t)(jlo + 1) * 32768, 32768, mbK1);
        MBAR_EXPECT(mbV, 32768);
        bulk_g2s(sb + 196608, vsrc + (size_t)jlo * 32768, 32768, mbV);
    }

    int rowA = (l & 7) + ((l >> 3) & 1) * 8;
    int colA = (l >> 4) * 8;
    int rowK = (l & 7) + ((l >> 4) & 1) * 8;
    int colK = ((l >> 3) & 1) * 8;
    uint32_t mA = (uint32_t)((rowA & 7) << 4);
    uint32_t mK = (uint32_t)((rowK & 7) << 4);

    uint32_t qh = sb + (uint32_t)((wid >> 1) * 32768 + ((wid & 1) * 16 + rowA) * 512);
    uint32_t ql = qh + 16384;
    uint32_t vh = sb + 196608 + (uint32_t)(rowA * 512);
    uint32_t vl = vh + 16384;

    float o[32][4];
#pragma unroll
    for (int i = 0; i < 32; i++)
#pragma unroll
        for (int j = 0; j < 4; j++) o[i][j] = 0.f;

    mbar_wait(mbQ, 0);
    uint32_t phv = 0;
    int r0g = qt * 128 + wid * 16 + (l >> 2);

    for (int kt = jlo; kt <= jhi; kt++) {
        int j0 = kt * 32;
        int kb = (kt - jlo) & 1;
        uint32_t mbK = kb ? mbK1 : mbK0;
        mbar_wait(mbK, (uint32_t)(((kt - jlo) >> 1) & 1));

        uint32_t kh = sb + 131072 + (uint32_t)(kb * 32768 + rowK * 512);
        uint32_t kl = kh + 16384;

        // ---- S = Q K^T (split-3), fragment-pipelined ----
        float sa[4][4];
#pragma unroll
        for (int i = 0; i < 4; i++)
#pragma unroll
            for (int j = 0; j < 4; j++) sa[i][j] = 0.f;

        uint32_t aH[2][4], aL[2][4], bh[2][8], bl[2][8];
        {
            uint32_t cbq = ((uint32_t)(colA * 2)) ^ mA;
            uint32_t cbk = ((uint32_t)(colK * 2)) ^ mK;
            ldsm4(aH[0], qh + cbq);
            ldsm4(aL[0], ql + cbq);
            ldsm4(bh[0],     kh + cbk);
            ldsm4(bh[0] + 4, kh + 8192 + cbk);
            ldsm4(bl[0],     kl + cbk);
            ldsm4(bl[0] + 4, kl + 8192 + cbk);
        }
#pragma unroll
        for (int kc = 0; kc < 16; kc++) {
            int cur = kc & 1, nxt = cur ^ 1;
            if (kc < 15) {
                uint32_t cbq = ((uint32_t)(colA * 2 + (kc + 1) * 32)) ^ mA;
                uint32_t cbk = ((uint32_t)(colK * 2 + (kc + 1) * 32)) ^ mK;
                ldsm4(aH[nxt], qh + cbq);
                ldsm4(aL[nxt], ql + cbq);
                ldsm4(bh[nxt],     kh + cbk);
                ldsm4(bh[nxt] + 4, kh + 8192 + cbk);
                ldsm4(bl[nxt],     kl + cbk);
                ldsm4(bl[nxt] + 4, kl + 8192 + cbk);
            }
#pragma unroll
            for (int tt = 0; tt < 4; tt++) {
                mma16816(sa[tt], aH[cur], bh[cur] + tt * 2);
                mma16816(sa[tt], aH[cur], bl[cur] + tt * 2);
                mma16816(sa[tt], aL[cur], bh[cur] + tt * 2);
            }
        }
        __syncthreads();                       // K(kt) consumed by all warps
        if (kt + 2 <= jhi && t == 0) {         // reload freed buffer with K(kt+2)
            MBAR_EXPECT(mbK, 32768);
            bulk_g2s(sb + 131072 + kb * 32768, ksrc + (size_t)(kt + 2) * 32768, 32768, mbK);
        }

        // ---- decay + causal mask + bf16 split, in registers ----
        uint32_t pH[2][4], pL[2][4];
#pragma unroll
        for (int tt = 0; tt < 4; tt++) {
            int c0 = j0 + tt * 8 + 2 * (l & 3);
            int d = r0g - c0;
            float e0 = exp2f((float)d * L2G);
            float e8 = e0 * G8C;
            float p0 = (d >= 0)  ? sa[tt][0] * e0 : 0.f;
            float p1 = (d >= 1)  ? sa[tt][1] * (e0 * IGAM) : 0.f;
            float p2 = (d >= -8) ? sa[tt][2] * e8 : 0.f;
            float p3 = (d >= -7) ? sa[tt][3] * (e8 * IGAM) : 0.f;
            uint32_t h01, l01, h23, l23;
            split2(p0, p1, h01, l01);
            split2(p2, p3, h23, l23);
            int c2 = tt >> 1, jj = tt & 1;
            pH[c2][2 * jj + 0] = h01;  pH[c2][2 * jj + 1] = h23;
            pL[c2][2 * jj + 0] = l01;  pL[c2][2 * jj + 1] = l23;
        }

        mbar_wait(mbV, phv); phv ^= 1;

        // ---- O += P V (split-3), V-fragment pipelined ----
        uint32_t vbh[2][4], vbl[2][4];
        {
            uint32_t cbv = ((uint32_t)(colA * 2)) ^ mA;
            ldsm4t(vbh[0], vh + cbv);
            ldsm4t(vbl[0], vl + cbv);
        }
#pragma unroll
        for (int idx = 0; idx < 32; idx++) {
            int c2 = idx >> 4, nb = idx & 15;
            int cur = idx & 1, nxt = cur ^ 1;
            if (idx < 31) {
                int c21 = (idx + 1) >> 4, nb1 = (idx + 1) & 15;
                uint32_t cbv = ((uint32_t)(colA * 2 + nb1 * 32)) ^ mA;
                ldsm4t(vbh[nxt], vh + c21 * 8192 + cbv);
                ldsm4t(vbl[nxt], vl + c21 * 8192 + cbv);
            }
            mma16816(o[2 * nb],     pH[c2], vbh[cur]);
            mma16816(o[2 * nb],     pH[c2], vbl[cur]);
            mma16816(o[2 * nb],     pL[c2], vbh[cur]);
            mma16816(o[2 * nb + 1], pH[c2], vbh[cur] + 2);
            mma16816(o[2 * nb + 1], pH[c2], vbl[cur] + 2);
            mma16816(o[2 * nb + 1], pL[c2], vbh[cur] + 2);
        }
        __syncthreads();                       // V consumed
        if (kt < jhi && t == 0) {
            MBAR_EXPECT(mbV, 32768);
            bulk_g2s(sb + 196608, vsrc + (size_t)(kt + 1) * 32768, 32768, mbV);
        }
    }

    float* ob = out + ((size_t)bn * S_LEN + r0g) * HID + 2 * (l & 3);
#pragma unroll
    for (int tt = 0; tt < 32; tt++) {
        *(float2*)(ob + tt * 8)           = make_float2(o[tt][0], o[tt][1]);
        *(float2*)(ob + 8 * HID + tt * 8) = make_float2(o[tt][2], o[tt][3]);
    }
}

// ---------------------------------------------------------------------------
extern "C" void kernel_launch(void* const* d_in, const int* in_sizes, int n_in,
                              void* d_out, int out_size) {
    const float* X  = (const float*)d_in[0];
    const float* Wq = (const float*)d_in[1];
    const float* Wk = (const float*)d_in[2];
    const float* Wv = (const float*)d_in[3];
    float* out = (float*)d_out;

    prep_kernel<<<5504, 256>>>(X, Wq, Wk, Wv);

    cudaFuncSetAttribute(proj_kernel, cudaFuncAttributeMaxDynamicSharedMemorySize, PROJ_SMEM);
    proj_kernel<<<dim3(3, 256), 256, PROJ_SMEM>>>();

    cudaFuncSetAttribute(attn_kernel, cudaFuncAttributeMaxDynamicSharedMemorySize, ATTN_SMEM);
    attn_kernel<<<16 * BN, 256, ATTN_SMEM>>>(out);
}

// round 16
// speedup vs baseline: 1.0083x; 1.0083x over previous
#include <cuda_runtime.h>
#include <cuda_bf16.h>
#include <math.h>
#include <stdint.h>

#define S_LEN 2048
#define HID   256
#define BN    16
#define M_ROWS (BN * S_LEN)   // 32768

#define L2G  (-0.04580369f)              // log2(0.96875)
#define IGAM (1.03225806451612903f)      // 1/0.96875
#define G8C  (0.775700596198439598f)     // 0.96875^8 (exact)

// ---------------------------------------------------------------------------
// Device-global scratch: PRE-SWIZZLED smem-image tiles.
// Image rule: byte offset of (row, col16B-unit) = row*R + (colb ^ ((row&7)<<4))
//   X images: [tile256][chunk4][plane2][128 rows x 128B]   (R=128)
//   W images: [mode3][nh2][chunk4][plane2][64 rows x 256B] (R=256)
//   Q/K/V images: [bn16][tile64][plane2][32 rows x 512B]   (R=512)
// ---------------------------------------------------------------------------
__device__ __align__(256) uint8_t g_Xi[33554432];
__device__ __align__(256) uint8_t g_Wi[786432];
__device__ __align__(256) uint8_t g_Qi[33554432];
__device__ __align__(256) uint8_t g_Ki[33554432];
__device__ __align__(256) uint8_t g_Vi[33554432];
__device__ float4 g_tab[S_LEN * 128];   // {sin, cos, scale, 1/scale}

// ---------------------------------------------------------------------------
// helpers
// ---------------------------------------------------------------------------
__device__ __forceinline__ uint32_t smem_u32(const void* p) {
    uint32_t a;
    asm("{ .reg .u64 t; cvta.to.shared.u64 t, %1; cvt.u32.u64 %0, t; }" : "=r"(a) : "l"(p));
    return a;
}
#define MBAR_INIT(mb, c) asm volatile("mbarrier.init.shared.b64 [%0], %1;" :: "r"(mb), "r"((uint32_t)(c)) : "memory")
#define MBAR_EXPECT(mb, bytes) \
    asm volatile("mbarrier.arrive.expect_tx.shared.b64 _, [%0], %1;" :: "r"(mb), "r"((uint32_t)(bytes)) : "memory")

__device__ __forceinline__ void bulk_g2s(uint32_t dst, const void* src, uint32_t bytes, uint32_t mbar) {
    asm volatile("cp.async.bulk.shared::cluster.global.mbarrier::complete_tx::bytes [%0], [%1], %2, [%3];"
                 :: "r"(dst), "l"(src), "r"(bytes), "r"(mbar) : "memory");
}
__device__ __forceinline__ void mbar_wait(uint32_t mb, uint32_t ph) {
    uint32_t done;
    asm volatile("{\n\t.reg .pred p;\n\tmbarrier.try_wait.parity.acquire.cta.shared::cta.b64 p, [%1], %2;\n\tselp.b32 %0, 1, 0, p;\n\t}"
                 : "=r"(done) : "r"(mb), "r"(ph) : "memory");
    if (!done) {
        asm volatile("{\n\t.reg .pred P1;\n\tWL%=:\n\tmbarrier.try_wait.parity.acquire.cta.shared::cta.b64 P1, [%0], %1, 0x989680;\n\t@P1 bra.uni WD%=;\n\tbra.uni WL%=;\n\tWD%=:\n\t}"
                     :: "r"(mb), "r"(ph) : "memory");
    }
}
__device__ __forceinline__ void ldsm4(uint32_t* r, uint32_t a) {
    asm volatile("ldmatrix.sync.aligned.m8n8.x4.shared.b16 {%0,%1,%2,%3}, [%4];"
                 : "=r"(r[0]), "=r"(r[1]), "=r"(r[2]), "=r"(r[3]) : "r"(a));
}
__device__ __forceinline__ void ldsm4t(uint32_t* r, uint32_t a) {
    asm volatile("ldmatrix.sync.aligned.m8n8.x4.trans.shared.b16 {%0,%1,%2,%3}, [%4];"
                 : "=r"(r[0]), "=r"(r[1]), "=r"(r[2]), "=r"(r[3]) : "r"(a));
}
__device__ __forceinline__ void mma16816(float* c, const uint32_t* a, const uint32_t* b) {
    asm volatile("mma.sync.aligned.m16n8k16.row.col.f32.bf16.bf16.f32 "
                 "{%0,%1,%2,%3}, {%4,%5,%6,%7}, {%8,%9}, {%0,%1,%2,%3};"
                 : "+f"(c[0]), "+f"(c[1]), "+f"(c[2]), "+f"(c[3])
                 : "r"(a[0]), "r"(a[1]), "r"(a[2]), "r"(a[3]), "r"(b[0]), "r"(b[1]));
}
__device__ __forceinline__ void split2(float a, float b, uint32_t& h, uint32_t& l) {
    __nv_bfloat162 hh = __floats2bfloat162_rn(a, b);
    __nv_bfloat162 ll = __floats2bfloat162_rn(a - __bfloat162float(hh.x),
                                              b - __bfloat162float(hh.y));
    h = *(uint32_t*)&hh;
    l = *(uint32_t*)&ll;
}

// ---------------------------------------------------------------------------
// Fused prep: X images (blocks 0..4095, 2 float4/thread) | tab | W images
// ---------------------------------------------------------------------------
__global__ void prep_kernel(const float* __restrict__ X,
                            const float* __restrict__ Wq,
                            const float* __restrict__ Wk,
                            const float* __restrict__ Wv) {
    int b = blockIdx.x;
    if (b < 4096) {
#pragma unroll
        for (int j = 0; j < 2; j++) {
            size_t i = ((size_t)b * 512 + threadIdx.x + j * 256) * 4;
            float4 v = *(const float4*)(X + i);
            uint2 hw, lw;
            split2(v.x, v.y, hw.x, lw.x);
            split2(v.z, v.w, hw.y, lw.y);
            int row = (int)(i >> 8), k0 = (int)(i & 255);
            int tile = row >> 7, r = row & 127;
            int chunk = k0 >> 6, kk = k0 & 63;
            uint32_t m = (uint32_t)((r & 7) << 4);
            uint32_t off = (uint32_t)(((tile * 4 + chunk) * 2) * 16384)
                         + (uint32_t)(r * 128) + (((uint32_t)(kk * 2)) ^ m);
            *(uint2*)(g_Xi + off)         = hw;
            *(uint2*)(g_Xi + off + 16384) = lw;
        }
    } else if (b < 5120) {
        int idx = (b - 4096) * 256 + threadIdx.x;
        int s = idx >> 7, i = idx & 127;
        float inv_freq = (float)exp2(-(double)i * (13.287712379549449 / 128.0));
        float sn, cs;
        sincosf((float)s * inv_freq, &sn, &cs);
        float base  = ((float)(2 * i) + 102.4f) / 358.4f;
        float scale = exp2f(log2f(base) * ((float)s * (1.0f / 512.0f)));
        g_tab[idx] = make_float4(sn, cs, scale, 1.0f / scale);
    } else {
        int idx = (b - 5120) * 256 + threadIdx.x;
        int mode = idx >> 15, pos = (idx & 32767) * 2;
        const float* W = (mode == 0) ? Wq : (mode == 1) ? Wk : Wv;
        float a = W[pos], c = W[pos + 1];
        uint32_t h, l;
        split2(a, c, h, l);
        int k = pos >> 8, n = pos & 255;
        int nh = n >> 7, nn = n & 127;
        int chunk = k >> 6, kr = k & 63;
        uint32_t m = (uint32_t)((kr & 7) << 4);
        uint32_t off = (uint32_t)((((mode * 2 + nh) * 4 + chunk) * 2) * 16384)
                     + (uint32_t)(kr * 256) + (((uint32_t)(nn * 2)) ^ m);
        *(uint32_t*)(g_Wi + off)         = h;
        *(uint32_t*)(g_Wi + off + 16384) = l;
    }
}

// ---------------------------------------------------------------------------
// Tensor-core QKV projection: TMA-bulk ring-3, 256 threads, split-3 bf16
// mma.sync with fragment pipelining, fused xpos epilogue. (R14 design)
// ---------------------------------------------------------------------------
#define PROJ_SMEM 196608

__global__ void __launch_bounds__(256, 1) proj_kernel() {
    extern __shared__ __align__(128) uint8_t smp[];
    __shared__ __align__(8) uint64_t mbs[3];
    uint32_t sb = smem_u32(smp);
    int t = threadIdx.x, wid = t >> 5, l = t & 31;
    int nh   = blockIdx.x;
    int mode = blockIdx.y;

    if (t == 0) {
#pragma unroll
        for (int i = 0; i < 3; i++) MBAR_INIT(smem_u32(&mbs[i]), 1);
    }
    __syncthreads();

    const uint8_t* xsrc = g_Xi + (size_t)(blockIdx.z * 4) * 32768;
    const uint8_t* wsrc = g_Wi + (size_t)((mode * 2 + nh) * 4) * 32768;

    if (t == 0) {
#pragma unroll
        for (int c = 0; c < 3; c++) {
            uint32_t mb = smem_u32(&mbs[c]);
            MBAR_EXPECT(mb, 65536);
            bulk_g2s(sb + c * 65536,         xsrc + c * 32768, 32768, mb);
            bulk_g2s(sb + c * 65536 + 32768, wsrc + c * 32768, 32768, mb);
        }
    }

    int rowA = (l & 7) + ((l >> 3) & 1) * 8;
    int colA = (l >> 4) * 8;
    uint32_t mX = (uint32_t)((rowA & 7) << 4);

    float o[16][4];
#pragma unroll
    for (int i = 0; i < 16; i++)
#pragma unroll
        for (int j = 0; j < 4; j++) o[i][j] = 0.f;

    for (int ch = 0; ch < 4; ch++) {
        int bf = ch % 3;
        mbar_wait(smem_u32(&mbs[bf]), (ch >= 3) ? 1u : 0u);

        uint32_t sX = sb + bf * 65536;
        uint32_t sW = sX + 32768;
        uint32_t xh = sX + (uint32_t)((wid * 16 + rowA) * 128);
        uint32_t xl = xh + 16384;

        uint32_t aH[2][4], aL[2][4], bh[2][4], bl[2][4];
        {
            uint32_t cbX = ((uint32_t)(colA * 2)) ^ mX;
            ldsm4(aH[0], xh + cbX);
            ldsm4(aL[0], xl + cbX);
            uint32_t cbW = ((uint32_t)(colA * 2)) ^ mX;
            ldsm4t(bh[0], sW + (uint32_t)(rowA * 256) + cbW);
            ldsm4t(bl[0], sW + 16384 + (uint32_t)(rowA * 256) + cbW);
        }
#pragma unroll
        for (int idx = 0; idx < 32; idx++) {
            int ks = idx >> 3, nb = idx & 7;
            int cur = idx & 1, nxt = cur ^ 1;
            int ksc = ks & 1;
            if (idx < 31) {
                int ks1 = (idx + 1) >> 3, nb1 = (idx + 1) & 7;
                uint32_t wrow1 = sW + (uint32_t)((rowA + ks1 * 16) * 256);
                uint32_t cbW1 = ((uint32_t)(colA * 2 + nb1 * 32)) ^ mX;
                ldsm4t(bh[nxt], wrow1 + cbW1);
                ldsm4t(bl[nxt], wrow1 + 16384 + cbW1);
                if (nb1 == 0) {
                    uint32_t cbX1 = ((uint32_t)(colA * 2 + ks1 * 32)) ^ mX;
                    ldsm4(aH[ks1 & 1], xh + cbX1);
                    ldsm4(aL[ks1 & 1], xl + cbX1);
                }
            }
            mma16816(o[2 * nb],     aH[ksc], bh[cur]);
            mma16816(o[2 * nb],     aH[ksc], bl[cur]);
            mma16816(o[2 * nb],     aL[ksc], bh[cur]);
            mma16816(o[2 * nb + 1], aH[ksc], bh[cur] + 2);
            mma16816(o[2 * nb + 1], aH[ksc], bl[cur] + 2);
            mma16816(o[2 * nb + 1], aL[ksc], bh[cur] + 2);
        }
        __syncthreads();
        if (ch + 3 < 4 && t == 0) {
            uint32_t mb = smem_u32(&mbs[bf]);
            MBAR_EXPECT(mb, 65536);
            bulk_g2s(sb + bf * 65536,         xsrc + (ch + 3) * 32768, 32768, mb);
            bulk_g2s(sb + bf * 65536 + 32768, wsrc + (ch + 3) * 32768, 32768, mb);
        }
    }

    // ---- epilogue: optional xpos rotation, split, store to Q/K/V images ----
    uint8_t* img = (mode == 0) ? g_Qi : (mode == 1) ? g_Ki : g_Vi;
    int tileg = (blockIdx.z >> 4) * 64 + (blockIdx.z & 15) * 4 + (wid >> 1);
    int r5 = (wid & 1) * 16 + (l >> 2);
    uint32_t m5 = (uint32_t)(((l >> 2) & 7) << 4);
    uint8_t* tb = img + (size_t)(tileg * 2) * 16384;
    int s1 = (blockIdx.z & 15) * 128 + wid * 16 + (l >> 2);
    int s2 = s1 + 8;

#pragma unroll
    for (int nb = 0; nb < 16; nb++) {
        int col = nh * 128 + nb * 8 + 2 * (l & 3);
        float a0 = o[nb][0], a1 = o[nb][1];
        float b0 = o[nb][2], b1 = o[nb][3];
        if (mode != 2) {
            float4 t1 = g_tab[s1 * 128 + (col >> 1)];
            float4 t2 = g_tab[s2 * 128 + (col >> 1)];
            float sc1 = (mode == 0) ? t1.z : t1.w;
            float sc2 = (mode == 0) ? t2.z : t2.w;
            float sn1 = t1.x * sc1, cs1 = t1.y * sc1;
            float sn2 = t2.x * sc2, cs2 = t2.y * sc2;
            float n0 = a0 * cs1 - a1 * sn1;
            float n1 = a1 * cs1 + a0 * sn1;
            float m0 = b0 * cs2 - b1 * sn2;
            float m1 = b1 * cs2 + b0 * sn2;
            a0 = n0; a1 = n1; b0 = m0; b1 = m1;
        }
        uint32_t h1, l1, h2, l2;
        split2(a0, a1, h1, l1);
        split2(b0, b1, h2, l2);
        uint32_t offc = ((uint32_t)(col * 2)) ^ m5;
        *(uint32_t*)(tb + r5 * 512 + offc)               = h1;
        *(uint32_t*)(tb + 16384 + r5 * 512 + offc)       = l1;
        *(uint32_t*)(tb + (r5 + 8) * 512 + offc)         = h2;
        *(uint32_t*)(tb + 16384 + (r5 + 8) * 512 + offc) = l2;
    }
}

// ---------------------------------------------------------------------------
// Raw mma.sync retention attention, frag-pipelined, UNIFIED K/V RING-3.
// smem: Q 128K + 3 x 32K ring = 224K, 1 CTA/SM. Items: K(kt),V(kt),K(kt+1)...
// prefetch distance 2 items -> each load has ~2 phases of lead time.
// ---------------------------------------------------------------------------
#define ATTN_SMEM 229376

__global__ void __launch_bounds__(256, 1) attn_kernel(float* __restrict__ out) {
    extern __shared__ __align__(128) uint8_t sma[];
    __shared__ __align__(8) uint64_t mba[4];   // Q, ring0, ring1, ring2
    uint32_t sb = smem_u32(sma);
    int t = threadIdx.x, wid = t >> 5, l = t & 31;

    int qt = 15 - (blockIdx.x >> 4);   // heavy q-tiles first
    int bn = blockIdx.x & 15;
    int jlo = max(0, qt * 4 - 8);      // drop d >= 257 (xpos damps further)
    int jhi = qt * 4 + 3;
    int nitems = 2 * (jhi - jlo + 1);

    if (t == 0) {
#pragma unroll
        for (int i = 0; i < 4; i++) MBAR_INIT(smem_u32(&mba[i]), 1);
    }
    __syncthreads();
    uint32_t mbQ = smem_u32(&mba[0]);

    const uint8_t* qsrc = g_Qi + (size_t)((bn * 64 + qt * 4) * 2) * 16384;
    const uint8_t* ksrc = g_Ki + (size_t)(bn * 64 * 2) * 16384;
    const uint8_t* vsrc = g_Vi + (size_t)(bn * 64 * 2) * 16384;

    auto issue = [&](int i) {
        int kt = jlo + (i >> 1);
        const uint8_t* src = ((i & 1) ? vsrc : ksrc) + (size_t)kt * 32768;
        int buf = i % 3;
        uint32_t mb = smem_u32(&mba[1 + buf]);
        MBAR_EXPECT(mb, 32768);
        bulk_g2s(sb + 131072 + buf * 32768, src, 32768, mb);
    };

    if (t == 0) {
        MBAR_EXPECT(mbQ, 131072);
        bulk_g2s(sb, qsrc, 131072, mbQ);
        issue(0); issue(1); issue(2);
    }

    int rowA = (l & 7) + ((l >> 3) & 1) * 8;
    int colA = (l >> 4) * 8;
    int rowK = (l & 7) + ((l >> 4) & 1) * 8;
    int colK = ((l >> 3) & 1) * 8;
    uint32_t mA = (uint32_t)((rowA & 7) << 4);
    uint32_t mK = (uint32_t)((rowK & 7) << 4);

    uint32_t qh = sb + (uint32_t)((wid >> 1) * 32768 + ((wid & 1) * 16 + rowA) * 512);
    uint32_t ql = qh + 16384;

    float o[32][4];
#pragma unroll
    for (int i = 0; i < 32; i++)
#pragma unroll
        for (int j = 0; j < 4; j++) o[i][j] = 0.f;

    mbar_wait(mbQ, 0);
    int r0g = qt * 128 + wid * 16 + (l >> 2);

    for (int kt = jlo; kt <= jhi; kt++) {
        int j0 = kt * 32;
        int iK = 2 * (kt - jlo);
        int bK = iK % 3;
        mbar_wait(smem_u32(&mba[1 + bK]), (uint32_t)((iK / 3) & 1));
        uint32_t kh = sb + 131072 + (uint32_t)(bK * 32768 + rowK * 512);
        uint32_t kl = kh + 16384;

        // ---- S = Q K^T (split-3), fragment-pipelined ----
        float sa[4][4];
#pragma unroll
        for (int i = 0; i < 4; i++)
#pragma unroll
            for (int j = 0; j < 4; j++) sa[i][j] = 0.f;

        uint32_t aH[2][4], aL[2][4], bh[2][8], bl[2][8];
        {
            uint32_t cbq = ((uint32_t)(colA * 2)) ^ mA;
            uint32_t cbk = ((uint32_t)(colK * 2)) ^ mK;
            ldsm4(aH[0], qh + cbq);
            ldsm4(aL[0], ql + cbq);
            ldsm4(bh[0],     kh + cbk);
            ldsm4(bh[0] + 4, kh + 8192 + cbk);
            ldsm4(bl[0],     kl + cbk);
            ldsm4(bl[0] + 4, kl + 8192 + cbk);
        }
#pragma unroll
        for (int kc = 0; kc < 16; kc++) {
            int cur = kc & 1, nxt = cur ^ 1;
            if (kc < 15) {
                uint32_t cbq = ((uint32_t)(colA * 2 + (kc + 1) * 32)) ^ mA;
                uint32_t cbk = ((uint32_t)(colK * 2 + (kc + 1) * 32)) ^ mK;
                ldsm4(aH[nxt], qh + cbq);
                ldsm4(aL[nxt], ql + cbq);
                ldsm4(bh[nxt],     kh + cbk);
                ldsm4(bh[nxt] + 4, kh + 8192 + cbk);
                ldsm4(bl[nxt],     kl + cbk);
                ldsm4(bl[nxt] + 4, kl + 8192 + cbk);
            }
#pragma unroll
            for (int tt = 0; tt < 4; tt++) {
                mma16816(sa[tt], aH[cur], bh[cur] + tt * 2);
                mma16816(sa[tt], aH[cur], bl[cur] + tt * 2);
                mma16816(sa[tt], aL[cur], bh[cur] + tt * 2);
            }
        }
        __syncthreads();                       // K(kt) consumed by all warps
        if (t == 0 && iK + 3 < nitems) issue(iK + 3);

        // ---- decay + causal mask + bf16 split, in registers ----
        uint32_t pH[2][4], pL[2][4];
#pragma unroll
        for (int tt = 0; tt < 4; tt++) {
            int c0 = j0 + tt * 8 + 2 * (l & 3);
            int d = r0g - c0;
            float e0 = exp2f((float)d * L2G);
            float e8 = e0 * G8C;
            float p0 = (d >= 0)  ? sa[tt][0] * e0 : 0.f;
            float p1 = (d >= 1)  ? sa[tt][1] * (e0 * IGAM) : 0.f;
            float p2 = (d >= -8) ? sa[tt][2] * e8 : 0.f;
            float p3 = (d >= -7) ? sa[tt][3] * (e8 * IGAM) : 0.f;
            uint32_t h01, l01, h23, l23;
            split2(p0, p1, h01, l01);
            split2(p2, p3, h23, l23);
            int c2 = tt >> 1, jj = tt & 1;
            pH[c2][2 * jj + 0] = h01;  pH[c2][2 * jj + 1] = h23;
            pL[c2][2 * jj + 0] = l01;  pL[c2][2 * jj + 1] = l23;
        }

        int iV = iK + 1;
        int bV = iV % 3;
        mbar_wait(smem_u32(&mba[1 + bV]), (uint32_t)((iV / 3) & 1));
        uint32_t vh = sb + 131072 + (uint32_t)(bV * 32768 + rowA * 512);
        uint32_t vl = vh + 16384;

        // ---- O += P V (split-3), V-fragment pipelined ----
        uint32_t vbh[2][4], vbl[2][4];
        {
            uint32_t cbv = ((uint32_t)(colA * 2)) ^ mA;
            ldsm4t(vbh[0], vh + cbv);
            ldsm4t(vbl[0], vl + cbv);
        }
#pragma unroll
        for (int idx = 0; idx < 32; idx++) {
            int c2 = idx >> 4, nb = idx & 15;
            int cur = idx & 1, nxt = cur ^ 1;
            if (idx < 31) {
                int c21 = (idx + 1) >> 4, nb1 = (idx + 1) & 15;
                uint32_t cbv = ((uint32_t)(colA * 2 + nb1 * 32)) ^ mA;
                ldsm4t(vbh[nxt], vh + c21 * 8192 + cbv);
                ldsm4t(vbl[nxt], vl + c21 * 8192 + cbv);
            }
            mma16816(o[2 * nb],     pH[c2], vbh[cur]);
            mma16816(o[2 * nb],     pH[c2], vbl[cur]);
            mma16816(o[2 * nb],     pL[c2], vbh[cur]);
            mma16816(o[2 * nb + 1], pH[c2], vbh[cur] + 2);
            mma16816(o[2 * nb + 1], pH[c2], vbl[cur] + 2);
            mma16816(o[2 * nb + 1], pL[c2], vbh[cur] + 2);
        }
        __syncthreads();                       // V(kt) consumed
        if (t == 0 && iV + 3 < nitems) issue(iV + 3);
    }

    float* ob = out + ((size_t)bn * S_LEN + r0g) * HID + 2 * (l & 3);
#pragma unroll
    for (int tt = 0; tt < 32; tt++) {
        *(float2*)(ob + tt * 8)           = make_float2(o[tt][0], o[tt][1]);
        *(float2*)(ob + 8 * HID + tt * 8) = make_float2(o[tt][2], o[tt][3]);
    }
}

// ---------------------------------------------------------------------------
extern "C" void kernel_launch(void* const* d_in, const int* in_sizes, int n_in,
                              void* d_out, int out_size) {
    const float* X  = (const float*)d_in[0];
    const float* Wq = (const float*)d_in[1];
    const float* Wk = (const float*)d_in[2];
    const float* Wv = (const float*)d_in[3];
    float* out = (float*)d_out;

    prep_kernel<<<5504, 256>>>(X, Wq, Wk, Wv);

    cudaFuncSetAttribute(proj_kernel, cudaFuncAttributeMaxDynamicSharedMemorySize, PROJ_SMEM);
    proj_kernel<<<dim3(2, 3, 256), 256, PROJ_SMEM>>>();

    cudaFuncSetAttribute(attn_kernel, cudaFuncAttributeMaxDynamicSharedMemorySize, ATTN_SMEM);
    attn_kernel<<<16 * BN, 256, ATTN_SMEM>>>(out);
}

// round 17
// speedup vs baseline: 1.0422x; 1.0336x over previous
#include <cuda_runtime.h>
#include <cuda_bf16.h>
#include <math.h>
#include <stdint.h>

#define S_LEN 2048
#define HID   256
#define BN    16
#define M_ROWS (BN * S_LEN)   // 32768

#define L2G  (-0.04580369f)              // log2(0.96875)
#define IGAM (1.03225806451612903f)      // 1/0.96875
#define G8C  (0.775700596198439598f)     // 0.96875^8 (exact)

// ---------------------------------------------------------------------------
// Device-global scratch: PRE-SWIZZLED smem-image tiles.
// Image rule: byte offset of (row, col16B-unit) = row*R + (colb ^ ((row&7)<<4))
//   X images: [tile256][chunk4][plane2][128 rows x 128B]   (R=128)
//   W images: [mode3][nh2][chunk4][plane2][64 rows x 256B] (R=256)
//   Q/K/V images: [bn16][tile64][plane2][32 rows x 512B]   (R=512)
// ---------------------------------------------------------------------------
__device__ __align__(256) uint8_t g_Xi[33554432];
__device__ __align__(256) uint8_t g_Wi[786432];
__device__ __align__(256) uint8_t g_Qi[33554432];
__device__ __align__(256) uint8_t g_Ki[33554432];
__device__ __align__(256) uint8_t g_Vi[33554432];
__device__ float4 g_tab[S_LEN * 128];   // {sin, cos, scale, 1/scale}

// ---------------------------------------------------------------------------
// helpers
// ---------------------------------------------------------------------------
__device__ __forceinline__ uint32_t smem_u32(const void* p) {
    uint32_t a;
    asm("{ .reg .u64 t; cvta.to.shared.u64 t, %1; cvt.u32.u64 %0, t; }" : "=r"(a) : "l"(p));
    return a;
}
#define MBAR_INIT(mb, c) asm volatile("mbarrier.init.shared.b64 [%0], %1;" :: "r"(mb), "r"((uint32_t)(c)) : "memory")
#define MBAR_EXPECT(mb, bytes) \
    asm volatile("mbarrier.arrive.expect_tx.shared.b64 _, [%0], %1;" :: "r"(mb), "r"((uint32_t)(bytes)) : "memory")

__device__ __forceinline__ void bulk_g2s(uint32_t dst, const void* src, uint32_t bytes, uint32_t mbar) {
    asm volatile("cp.async.bulk.shared::cluster.global.mbarrier::complete_tx::bytes [%0], [%1], %2, [%3];"
                 :: "r"(dst), "l"(src), "r"(bytes), "r"(mbar) : "memory");
}
__device__ __forceinline__ void mbar_wait(uint32_t mb, uint32_t ph) {
    uint32_t done;
    asm volatile("{\n\t.reg .pred p;\n\tmbarrier.try_wait.parity.acquire.cta.shared::cta.b64 p, [%1], %2;\n\tselp.b32 %0, 1, 0, p;\n\t}"
                 : "=r"(done) : "r"(mb), "r"(ph) : "memory");
    if (!done) {
        asm volatile("{\n\t.reg .pred P1;\n\tWL%=:\n\tmbarrier.try_wait.parity.acquire.cta.shared::cta.b64 P1, [%0], %1, 0x989680;\n\t@P1 bra.uni WD%=;\n\tbra.uni WL%=;\n\tWD%=:\n\t}"
                     :: "r"(mb), "r"(ph) : "memory");
    }
}
__device__ __forceinline__ void ldsm4(uint32_t* r, uint32_t a) {
    asm volatile("ldmatrix.sync.aligned.m8n8.x4.shared.b16 {%0,%1,%2,%3}, [%4];"
                 : "=r"(r[0]), "=r"(r[1]), "=r"(r[2]), "=r"(r[3]) : "r"(a));
}
__device__ __forceinline__ void ldsm4t(uint32_t* r, uint32_t a) {
    asm volatile("ldmatrix.sync.aligned.m8n8.x4.trans.shared.b16 {%0,%1,%2,%3}, [%4];"
                 : "=r"(r[0]), "=r"(r[1]), "=r"(r[2]), "=r"(r[3]) : "r"(a));
}
__device__ __forceinline__ void mma16816(float* c, const uint32_t* a, const uint32_t* b) {
    asm volatile("mma.sync.aligned.m16n8k16.row.col.f32.bf16.bf16.f32 "
                 "{%0,%1,%2,%3}, {%4,%5,%6,%7}, {%8,%9}, {%0,%1,%2,%3};"
                 : "+f"(c[0]), "+f"(c[1]), "+f"(c[2]), "+f"(c[3])
                 : "r"(a[0]), "r"(a[1]), "r"(a[2]), "r"(a[3]), "r"(b[0]), "r"(b[1]));
}
__device__ __forceinline__ void split2(float a, float b, uint32_t& h, uint32_t& l) {
    __nv_bfloat162 hh = __floats2bfloat162_rn(a, b);
    __nv_bfloat162 ll = __floats2bfloat162_rn(a - __bfloat162float(hh.x),
                                              b - __bfloat162float(hh.y));
    h = *(uint32_t*)&hh;
    l = *(uint32_t*)&ll;
}

// ---------------------------------------------------------------------------
// Fused prep: X images (blocks 0..2047, 4 float4/thread) | tab | W images
// ---------------------------------------------------------------------------
__global__ void prep_kernel(const float* __restrict__ X,
                            const float* __restrict__ Wq,
                            const float* __restrict__ Wk,
                            const float* __restrict__ Wv) {
    int b = blockIdx.x;
    if (b < 2048) {
#pragma unroll
        for (int j = 0; j < 4; j++) {
            size_t i = ((size_t)b * 1024 + threadIdx.x + j * 256) * 4;
            float4 v = *(const float4*)(X + i);
            uint2 hw, lw;
            split2(v.x, v.y, hw.x, lw.x);
            split2(v.z, v.w, hw.y, lw.y);
            int row = (int)(i >> 8), k0 = (int)(i & 255);
            int tile = row >> 7, r = row & 127;
            int chunk = k0 >> 6, kk = k0 & 63;
            uint32_t m = (uint32_t)((r & 7) << 4);
            uint32_t off = (uint32_t)(((tile * 4 + chunk) * 2) * 16384)
                         + (uint32_t)(r * 128) + (((uint32_t)(kk * 2)) ^ m);
            *(uint2*)(g_Xi + off)         = hw;
            *(uint2*)(g_Xi + off + 16384) = lw;
        }
    } else if (b < 3072) {
        int idx = (b - 2048) * 256 + threadIdx.x;
        int s = idx >> 7, i = idx & 127;
        float inv_freq = (float)exp2(-(double)i * (13.287712379549449 / 128.0));
        float sn, cs;
        sincosf((float)s * inv_freq, &sn, &cs);
        float base  = ((float)(2 * i) + 102.4f) / 358.4f;
        float scale = exp2f(log2f(base) * ((float)s * (1.0f / 512.0f)));
        g_tab[idx] = make_float4(sn, cs, scale, 1.0f / scale);
    } else {
        int idx = (b - 3072) * 256 + threadIdx.x;
        int mode = idx >> 15, pos = (idx & 32767) * 2;
        const float* W = (mode == 0) ? Wq : (mode == 1) ? Wk : Wv;
        float a = W[pos], c = W[pos + 1];
        uint32_t h, l;
        split2(a, c, h, l);
        int k = pos >> 8, n = pos & 255;
        int nh = n >> 7, nn = n & 127;
        int chunk = k >> 6, kr = k & 63;
        uint32_t m = (uint32_t)((kr & 7) << 4);
        uint32_t off = (uint32_t)((((mode * 2 + nh) * 4 + chunk) * 2) * 16384)
                     + (uint32_t)(kr * 256) + (((uint32_t)(nn * 2)) ^ m);
        *(uint32_t*)(g_Wi + off)         = h;
        *(uint32_t*)(g_Wi + off + 16384) = l;
    }
}

// ---------------------------------------------------------------------------
// Tensor-core QKV projection: TMA-bulk ring-3, 256 threads, split-3 bf16
// mma.sync with fragment pipelining + reordered accumulation, xpos epilogue.
// ---------------------------------------------------------------------------
#define PROJ_SMEM 196608

__global__ void __launch_bounds__(256, 1) proj_kernel() {
    extern __shared__ __align__(128) uint8_t smp[];
    __shared__ __align__(8) uint64_t mbs[3];
    uint32_t sb = smem_u32(smp);
    int t = threadIdx.x, wid = t >> 5, l = t & 31;
    int nh   = blockIdx.x;
    int mode = blockIdx.y;

    if (t == 0) {
#pragma unroll
        for (int i = 0; i < 3; i++) MBAR_INIT(smem_u32(&mbs[i]), 1);
    }
    __syncthreads();

    const uint8_t* xsrc = g_Xi + (size_t)(blockIdx.z * 4) * 32768;
    const uint8_t* wsrc = g_Wi + (size_t)((mode * 2 + nh) * 4) * 32768;

    if (t == 0) {
#pragma unroll
        for (int c = 0; c < 3; c++) {
            uint32_t mb = smem_u32(&mbs[c]);
            MBAR_EXPECT(mb, 65536);
            bulk_g2s(sb + c * 65536,         xsrc + c * 32768, 32768, mb);
            bulk_g2s(sb + c * 65536 + 32768, wsrc + c * 32768, 32768, mb);
        }
    }

    int rowA = (l & 7) + ((l >> 3) & 1) * 8;
    int colA = (l >> 4) * 8;
    uint32_t mX = (uint32_t)((rowA & 7) << 4);

    float o[16][4];
#pragma unroll
    for (int i = 0; i < 16; i++)
#pragma unroll
        for (int j = 0; j < 4; j++) o[i][j] = 0.f;

    for (int ch = 0; ch < 4; ch++) {
        int bf = ch % 3;
        mbar_wait(smem_u32(&mbs[bf]), (ch >= 3) ? 1u : 0u);

        uint32_t sX = sb + bf * 65536;
        uint32_t sW = sX + 32768;
        uint32_t xh = sX + (uint32_t)((wid * 16 + rowA) * 128);
        uint32_t xl = xh + 16384;

        uint32_t aH[2][4], aL[2][4], bh[2][4], bl[2][4];
        {
            uint32_t cbX = ((uint32_t)(colA * 2)) ^ mX;
            ldsm4(aH[0], xh + cbX);
            ldsm4(aL[0], xl + cbX);
            uint32_t cbW = ((uint32_t)(colA * 2)) ^ mX;
            ldsm4t(bh[0], sW + (uint32_t)(rowA * 256) + cbW);
            ldsm4t(bl[0], sW + 16384 + (uint32_t)(rowA * 256) + cbW);
        }
#pragma unroll
        for (int idx = 0; idx < 32; idx++) {
            int ks = idx >> 3, nb = idx & 7;
            int cur = idx & 1, nxt = cur ^ 1;
            int ksc = ks & 1;
            if (idx < 31) {
                int ks1 = (idx + 1) >> 3, nb1 = (idx + 1) & 7;
                uint32_t wrow1 = sW + (uint32_t)((rowA + ks1 * 16) * 256);
                uint32_t cbW1 = ((uint32_t)(colA * 2 + nb1 * 32)) ^ mX;
                ldsm4t(bh[nxt], wrow1 + cbW1);
                ldsm4t(bl[nxt], wrow1 + 16384 + cbW1);
                if (nb1 == 0) {
                    uint32_t cbX1 = ((uint32_t)(colA * 2 + ks1 * 32)) ^ mX;
                    ldsm4(aH[ks1 & 1], xh + cbX1);
                    ldsm4(aL[ks1 & 1], xl + cbX1);
                }
            }
            // reordered: alternate accumulators to widen RAW distance
            mma16816(o[2 * nb],     aH[ksc], bh[cur]);
            mma16816(o[2 * nb + 1], aH[ksc], bh[cur] + 2);
            mma16816(o[2 * nb],     aH[ksc], bl[cur]);
            mma16816(o[2 * nb + 1], aH[ksc], bl[cur] + 2);
            mma16816(o[2 * nb],     aL[ksc], bh[cur]);
            mma16816(o[2 * nb + 1], aL[ksc], bh[cur] + 2);
        }
        __syncthreads();
        if (ch + 3 < 4 && t == 0) {
            uint32_t mb = smem_u32(&mbs[bf]);
            MBAR_EXPECT(mb, 65536);
            bulk_g2s(sb + bf * 65536,         xsrc + (ch + 3) * 32768, 32768, mb);
            bulk_g2s(sb + bf * 65536 + 32768, wsrc + (ch + 3) * 32768, 32768, mb);
        }
    }

    // ---- epilogue: optional xpos rotation, split, store to Q/K/V images ----
    uint8_t* img = (mode == 0) ? g_Qi : (mode == 1) ? g_Ki : g_Vi;
    int tileg = (blockIdx.z >> 4) * 64 + (blockIdx.z & 15) * 4 + (wid >> 1);
    int r5 = (wid & 1) * 16 + (l >> 2);
    uint32_t m5 = (uint32_t)(((l >> 2) & 7) << 4);
    uint8_t* tb = img + (size_t)(tileg * 2) * 16384;
    int s1 = (blockIdx.z & 15) * 128 + wid * 16 + (l >> 2);
    int s2 = s1 + 8;

#pragma unroll
    for (int nb = 0; nb < 16; nb++) {
        int col = nh * 128 + nb * 8 + 2 * (l & 3);
        float a0 = o[nb][0], a1 = o[nb][1];
        float b0 = o[nb][2], b1 = o[nb][3];
        if (mode != 2) {
            float4 t1 = g_tab[s1 * 128 + (col >> 1)];
            float4 t2 = g_tab[s2 * 128 + (col >> 1)];
            float sc1 = (mode == 0) ? t1.z : t1.w;
            float sc2 = (mode == 0) ? t2.z : t2.w;
            float sn1 = t1.x * sc1, cs1 = t1.y * sc1;
            float sn2 = t2.x * sc2, cs2 = t2.y * sc2;
            float n0 = a0 * cs1 - a1 * sn1;
            float n1 = a1 * cs1 + a0 * sn1;
            float m0 = b0 * cs2 - b1 * sn2;
            float m1 = b1 * cs2 + b0 * sn2;
            a0 = n0; a1 = n1; b0 = m0; b1 = m1;
        }
        uint32_t h1, l1, h2, l2;
        split2(a0, a1, h1, l1);
        split2(b0, b1, h2, l2);
        uint32_t offc = ((uint32_t)(col * 2)) ^ m5;
        *(uint32_t*)(tb + r5 * 512 + offc)               = h1;
        *(uint32_t*)(tb + 16384 + r5 * 512 + offc)       = l1;
        *(uint32_t*)(tb + (r5 + 8) * 512 + offc)         = h2;
        *(uint32_t*)(tb + 16384 + (r5 + 8) * 512 + offc) = l2;
    }
}

// ---------------------------------------------------------------------------
// Raw mma.sync retention attention (R14 structure): frag-pipelined,
// K double-buffered, window 224 (jlo = qt*4-7).
// smem: Q 128K + K0 32K + K1 32K + V 32K = 224K, 1 CTA/SM.
// ---------------------------------------------------------------------------
#define ATTN_SMEM 229376

__global__ void __launch_bounds__(256, 1) attn_kernel(float* __restrict__ out) {
    extern __shared__ __align__(128) uint8_t sma[];
    __shared__ __align__(8) uint64_t mba[4];   // Q, K0, K1, V
    uint32_t sb = smem_u32(sma);
    int t = threadIdx.x, wid = t >> 5, l = t & 31;

    int qt = 15 - (blockIdx.x >> 4);   // heavy q-tiles first
    int bn = blockIdx.x & 15;
    int jlo = max(0, qt * 4 - 7);      // window 224: drop d >= 225 (xpos damps ~4x)
    int jhi = qt * 4 + 3;

    if (t == 0) {
#pragma unroll
        for (int i = 0; i < 4; i++) MBAR_INIT(smem_u32(&mba[i]), 1);
    }
    __syncthreads();
    uint32_t mbQ  = smem_u32(&mba[0]);
    uint32_t mbK0 = smem_u32(&mba[1]);
    uint32_t mbK1 = smem_u32(&mba[2]);
    uint32_t mbV  = smem_u32(&mba[3]);

    const uint8_t* qsrc = g_Qi + (size_t)((bn * 64 + qt * 4) * 2) * 16384;
    const uint8_t* ksrc = g_Ki + (size_t)(bn * 64 * 2) * 16384;
    const uint8_t* vsrc = g_Vi + (size_t)(bn * 64 * 2) * 16384;

    if (t == 0) {
        MBAR_EXPECT(mbQ, 131072);
        bulk_g2s(sb, qsrc, 131072, mbQ);
        MBAR_EXPECT(mbK0, 32768);
        bulk_g2s(sb + 131072, ksrc + (size_t)jlo * 32768, 32768, mbK0);
        MBAR_EXPECT(mbK1, 32768);
        bulk_g2s(sb + 163840, ksrc + (size_t)(jlo + 1) * 32768, 32768, mbK1);
        MBAR_EXPECT(mbV, 32768);
        bulk_g2s(sb + 196608, vsrc + (size_t)jlo * 32768, 32768, mbV);
    }

    int rowA = (l & 7) + ((l >> 3) & 1) * 8;
    int colA = (l >> 4) * 8;
    int rowK = (l & 7) + ((l >> 4) & 1) * 8;
    int colK = ((l >> 3) & 1) * 8;
    uint32_t mA = (uint32_t)((rowA & 7) << 4);
    uint32_t mK = (uint32_t)((rowK & 7) << 4);

    uint32_t qh = sb + (uint32_t)((wid >> 1) * 32768 + ((wid & 1) * 16 + rowA) * 512);
    uint32_t ql = qh + 16384;
    uint32_t vh = sb + 196608 + (uint32_t)(rowA * 512);
    uint32_t vl = vh + 16384;

    float o[32][4];
#pragma unroll
    for (int i = 0; i < 32; i++)
#pragma unroll
        for (int j = 0; j < 4; j++) o[i][j] = 0.f;

    mbar_wait(mbQ, 0);
    uint32_t phv = 0;
    int r0g = qt * 128 + wid * 16 + (l >> 2);

    for (int kt = jlo; kt <= jhi; kt++) {
        int j0 = kt * 32;
        int kb = (kt - jlo) & 1;
        uint32_t mbK = kb ? mbK1 : mbK0;
        mbar_wait(mbK, (uint32_t)(((kt - jlo) >> 1) & 1));

        uint32_t kh = sb + 131072 + (uint32_t)(kb * 32768 + rowK * 512);
        uint32_t kl = kh + 16384;

        // ---- S = Q K^T (split-3), fragment-pipelined ----
        float sa[4][4];
#pragma unroll
        for (int i = 0; i < 4; i++)
#pragma unroll
            for (int j = 0; j < 4; j++) sa[i][j] = 0.f;

        uint32_t aH[2][4], aL[2][4], bh[2][8], bl[2][8];
        {
            uint32_t cbq = ((uint32_t)(colA * 2)) ^ mA;
            uint32_t cbk = ((uint32_t)(colK * 2)) ^ mK;
            ldsm4(aH[0], qh + cbq);
            ldsm4(aL[0], ql + cbq);
            ldsm4(bh[0],     kh + cbk);
            ldsm4(bh[0] + 4, kh + 8192 + cbk);
            ldsm4(bl[0],     kl + cbk);
            ldsm4(bl[0] + 4, kl + 8192 + cbk);
        }
#pragma unroll
        for (int kc = 0; kc < 16; kc++) {
            int cur = kc & 1, nxt = cur ^ 1;
            if (kc < 15) {
                uint32_t cbq = ((uint32_t)(colA * 2 + (kc + 1) * 32)) ^ mA;
                uint32_t cbk = ((uint32_t)(colK * 2 + (kc + 1) * 32)) ^ mK;
                ldsm4(aH[nxt], qh + cbq);
                ldsm4(aL[nxt], ql + cbq);
                ldsm4(bh[nxt],     kh + cbk);
                ldsm4(bh[nxt] + 4, kh + 8192 + cbk);
                ldsm4(bl[nxt],     kl + cbk);
                ldsm4(bl[nxt] + 4, kl + 8192 + cbk);
            }
            // reordered: sweep tt inside each split pass (max RAW distance)
#pragma unroll
            for (int tt = 0; tt < 4; tt++) mma16816(sa[tt], aH[cur], bh[cur] + tt * 2);
#pragma unroll
            for (int tt = 0; tt < 4; tt++) mma16816(sa[tt], aH[cur], bl[cur] + tt * 2);
#pragma unroll
            for (int tt = 0; tt < 4; tt++) mma16816(sa[tt], aL[cur], bh[cur] + tt * 2);
        }
        __syncthreads();                       // K(kt) consumed by all warps
        if (kt + 2 <= jhi && t == 0) {         // reload freed buffer with K(kt+2)
            MBAR_EXPECT(mbK, 32768);
            bulk_g2s(sb + 131072 + kb * 32768, ksrc + (size_t)(kt + 2) * 32768, 32768, mbK);
        }

        // ---- decay + causal mask + bf16 split, in registers ----
        uint32_t pH[2][4], pL[2][4];
#pragma unroll
        for (int tt = 0; tt < 4; tt++) {
            int c0 = j0 + tt * 8 + 2 * (l & 3);
            int d = r0g - c0;
            float e0 = exp2f((float)d * L2G);
            float e8 = e0 * G8C;
            float p0 = (d >= 0)  ? sa[tt][0] * e0 : 0.f;
            float p1 = (d >= 1)  ? sa[tt][1] * (e0 * IGAM) : 0.f;
            float p2 = (d >= -8) ? sa[tt][2] * e8 : 0.f;
            float p3 = (d >= -7) ? sa[tt][3] * (e8 * IGAM) : 0.f;
            uint32_t h01, l01, h23, l23;
            split2(p0, p1, h01, l01);
            split2(p2, p3, h23, l23);
            int c2 = tt >> 1, jj = tt & 1;
            pH[c2][2 * jj + 0] = h01;  pH[c2][2 * jj + 1] = h23;
            pL[c2][2 * jj + 0] = l01;  pL[c2][2 * jj + 1] = l23;
        }

        mbar_wait(mbV, phv); phv ^= 1;

        // ---- O += P V (split-3), V-fragment pipelined, reordered ----
        uint32_t vbh[2][4], vbl[2][4];
        {
            uint32_t cbv = ((uint32_t)(colA * 2)) ^ mA;
            ldsm4t(vbh[0], vh + cbv);
            ldsm4t(vbl[0], vl + cbv);
        }
#pragma unroll
        for (int idx = 0; idx < 32; idx++) {
            int c2 = idx >> 4, nb = idx & 15;
            int cur = idx & 1, nxt = cur ^ 1;
            if (idx < 31) {
                int c21 = (idx + 1) >> 4, nb1 = (idx + 1) & 15;
                uint32_t cbv = ((uint32_t)(colA * 2 + nb1 * 32)) ^ mA;
                ldsm4t(vbh[nxt], vh + c21 * 8192 + cbv);
                ldsm4t(vbl[nxt], vl + c21 * 8192 + cbv);
            }
            mma16816(o[2 * nb],     pH[c2], vbh[cur]);
            mma16816(o[2 * nb + 1], pH[c2], vbh[cur] + 2);
            mma16816(o[2 * nb],     pH[c2], vbl[cur]);
            mma16816(o[2 * nb + 1], pH[c2], vbl[cur] + 2);
            mma16816(o[2 * nb],     pL[c2], vbh[cur]);
            mma16816(o[2 * nb + 1], pL[c2], vbh[cur] + 2);
        }
        __syncthreads();                       // V consumed
        if (kt < jhi && t == 0) {
            MBAR_EXPECT(mbV, 32768);
            bulk_g2s(sb + 196608, vsrc + (size_t)(kt + 1) * 32768, 32768, mbV);
        }
    }

    float* ob = out + ((size_t)bn * S_LEN + r0g) * HID + 2 * (l & 3);
#pragma unroll
    for (int tt = 0; tt < 32; tt++) {
        *(float2*)(ob + tt * 8)           = make_float2(o[tt][0], o[tt][1]);
        *(float2*)(ob + 8 * HID + tt * 8) = make_float2(o[tt][2], o[tt][3]);
    }
}

// ---------------------------------------------------------------------------
extern "C" void kernel_launch(void* const* d_in, const int* in_sizes, int n_in,
                              void* d_out, int out_size) {
    const float* X  = (const float*)d_in[0];
    const float* Wq = (const float*)d_in[1];
    const float* Wk = (const float*)d_in[2];
    const float* Wv = (const float*)d_in[3];
    float* out = (float*)d_out;

    prep_kernel<<<3456, 256>>>(X, Wq, Wk, Wv);

    cudaFuncSetAttribute(proj_kernel, cudaFuncAttributeMaxDynamicSharedMemorySize, PROJ_SMEM);
    proj_kernel<<<dim3(2, 3, 256), 256, PROJ_SMEM>>>();

    cudaFuncSetAttribute(attn_kernel, cudaFuncAttributeMaxDynamicSharedMemorySize, ATTN_SMEM);
    attn_kernel<<<16 * BN, 256, ATTN_SMEM>>>(out);
}